// round 9
// baseline (speedup 1.0000x reference)
#include <cuda_runtime.h>
#include <cstdint>

// Problem-instance constants (fixed by setup_inputs)
#define NMAX 50000
#define JDIM 25000
#define IDIM 12500
#define DD   128
#define E1_CNT 600000
#define E2_CNT 300000
#define MASK_CNT (JDIM * DD)       // 3,200,000 dropout mask elements

// ---------------- scratch (device globals; no allocation allowed) ----------
__device__ __align__(16) float g_agg1[JDIM * DD];
__device__ __align__(16) float g_deg1[JDIM];
__device__ __align__(16) float g_x1[JDIM * DD];
__device__ __align__(16) float g_agg2[IDIM * DD];
__device__ __align__(16) float g_deg2[IDIM];
__device__ __align__(16) unsigned char g_keep[JDIM * DD];
__device__ int g_mode;   // 0 = int64, 1 = int32, 2 = float32

// ---------------- index-dtype detection ------------------------------------
// float32 indices (values mostly >= 2.0): words >= 0x40000000 appear.
// int64 indices (< 2^31): every odd 32-bit word is 0.
// int32 indices: odd words are random small node ids (nonzero, < 2^30).
__global__ void detect_kernel(const unsigned int* __restrict__ a, int nwords) {
    __shared__ int any_large, any_odd_nz;
    if (threadIdx.x == 0) { any_large = 0; any_odd_nz = 0; }
    __syncthreads();
    int limit = nwords < 4096 ? nwords : 4096;
    for (int t = threadIdx.x; t < limit; t += blockDim.x) {
        unsigned int w = a[t];
        if (w >= 0x40000000u) any_large = 1;
        if ((t & 1) && w != 0u) any_odd_nz = 1;
    }
    __syncthreads();
    if (threadIdx.x == 0)
        g_mode = any_large ? 2 : (any_odd_nz ? 1 : 0);
}

// ---------------- zero scratch ---------------------------------------------
__global__ void zero_kernel() {
    int i = blockIdx.x * blockDim.x + threadIdx.x;
    int stride = gridDim.x * blockDim.x;
    float4 z = make_float4(0.f, 0.f, 0.f, 0.f);
    for (int t = i; t < JDIM * DD / 4; t += stride) ((float4*)g_agg1)[t] = z;
    for (int t = i; t < IDIM * DD / 4; t += stride) ((float4*)g_agg2)[t] = z;
    for (int t = i; t < JDIM; t += stride) g_deg1[t] = 0.f;
    for (int t = i; t < IDIM; t += stride) g_deg2[t] = 0.f;
}

// ---------------- threefry2x32 dropout mask --------------------------------
// Modern JAX default: threefry_partitionable. For 32-bit random_bits the
// per-element counter is the 64-bit flat index i -> (x0, x1) = (hi, lo) =
// (0, i); key = jax.random.key(1) -> (k0, k1) = (0, 1); output word is the
// XOR-fold  bits = y0 ^ y1.  uniform<0.5  <=>  MSB(bits) == 0.
__global__ void mask_kernel() {
    int i = blockIdx.x * blockDim.x + threadIdx.x;
    if (i >= MASK_CNT) return;
    uint32_t x0 = 0u;               // hi 32 bits of counter (always 0 here)
    uint32_t x1 = (uint32_t)i;      // lo 32 bits of counter
    const uint32_t ks0 = 0u, ks1 = 1u, ks2 = 0x1BD11BDBu; // 0^1^0x1BD11BDA

#define TF_ROUND(r) { x0 += x1; x1 = __funnelshift_l(x1, x1, (r)); x1 ^= x0; }
#define TF_G0 TF_ROUND(13) TF_ROUND(15) TF_ROUND(26) TF_ROUND(6)
#define TF_G1 TF_ROUND(17) TF_ROUND(29) TF_ROUND(16) TF_ROUND(24)

    x0 += ks0; x1 += ks1;
    TF_G0
    x0 += ks1; x1 += ks2 + 1u;
    TF_G1
    x0 += ks2; x1 += ks0 + 2u;
    TF_G0
    x0 += ks0; x1 += ks1 + 3u;
    TF_G1
    x0 += ks1; x1 += ks2 + 4u;
    TF_G0
    x0 += ks2; x1 += ks0 + 5u;

    uint32_t bits = x0 ^ x1;        // partitionable 32-bit XOR-fold
    g_keep[i] = (unsigned char)(1u ^ (bits >> 31));
#undef TF_G1
#undef TF_G0
#undef TF_ROUND
}

// ---------------- scatter-mean accumulation (one warp per edge) ------------
template <int LAYER>
__global__ void scatter_kernel(const float* __restrict__ xext,
                               const void* __restrict__ ei_raw, int E) {
    int w = (int)((blockIdx.x * (unsigned)blockDim.x + threadIdx.x) >> 5);
    if (w >= E) return;

    long long src, dst;
    int mode = g_mode;
    if (mode == 0) {
        const long long* ei = (const long long*)ei_raw;
        src = ei[w];
        dst = ei[(long long)E + w];
    } else if (mode == 1) {
        const int* ei = (const int*)ei_raw;
        src = ei[w];
        dst = ei[E + w];
    } else {
        const float* ei = (const float*)ei_raw;
        src = (long long)ei[w];
        dst = (long long)ei[E + w];
    }

    const int dlim = (LAYER == 1) ? JDIM : IDIM;
    const int slim = (LAYER == 1) ? NMAX : JDIM;
    if ((unsigned long long)dst >= (unsigned long long)dlim) return;
    if ((unsigned long long)src >= (unsigned long long)slim) return;

    const float* x = (LAYER == 1) ? xext : g_x1;
    float* agg = (LAYER == 1) ? g_agg1 : g_agg2;
    float* deg = (LAYER == 1) ? g_deg1 : g_deg2;

    int lane = threadIdx.x & 31;
    float4 v = ((const float4*)(x + src * DD))[lane];
    atomicAdd((float4*)(agg + dst * DD) + lane, v);  // RED.E.ADD (no return)
    if (lane == 0) atomicAdd(deg + dst, 1.0f);
}

// ---------------- fused stacked GEMM ---------------------------------------
// out[r,c] = sum_k aggm[r,k]*Wl[c,k] + sum_k x[r,k]*Wr[c,k] + b[c]
// Stacked K=256: A=[aggm | x], B[k][c] = (k<128 ? Wl[c][k] : Wr[c][k-128]).
// Layer 1: relu + dropout epilogue -> g_x1. Layer 2: -> d_out.
#define WPAD 129    // padded row stride for Wsh (conflict-free)
#define BM   64     // rows per block

template <int LAYER>
__global__ __launch_bounds__(256, 1)
void gemm_kernel(const float* __restrict__ xext,
                 const float* __restrict__ Wl, const float* __restrict__ Wr,
                 const float* __restrict__ bias, float* __restrict__ outext) {
    extern __shared__ float sm[];
    float* Wsh = sm;                    // [256][WPAD]
    float* Ash = sm + 256 * WPAD;       // [BM][256]

    const int M = (LAYER == 1) ? JDIM : IDIM;
    const float* agg = (LAYER == 1) ? g_agg1 : g_agg2;
    const float* deg = (LAYER == 1) ? g_deg1 : g_deg2;
    const float* xin = (LAYER == 1) ? xext : g_x1;
    float* out = (LAYER == 1) ? g_x1 : outext;

    const int tid = threadIdx.x;
    const int blockRow = blockIdx.x * BM;

    // Load W stacked+transposed into Wsh[k][c], coalesced float4 along k.
    for (int q = tid; q < 8192; q += 256) {
        int m  = q >> 12;           // 0 = Wl, 1 = Wr
        int qq = q & 4095;
        int c  = qq >> 5;           // 0..127
        int kq = qq & 31;           // float4 index along k
        const float* src = (m ? Wr : Wl) + c * DD;
        float4 v = ((const float4*)src)[kq];
        int k0 = m * 128 + kq * 4;
        Wsh[(k0 + 0) * WPAD + c] = v.x;
        Wsh[(k0 + 1) * WPAD + c] = v.y;
        Wsh[(k0 + 2) * WPAD + c] = v.z;
        Wsh[(k0 + 3) * WPAD + c] = v.w;
    }

    // Load A tile [BM][256]: k<128 = agg*invdeg, k>=128 = x row.
    for (int q = tid; q < BM * 64; q += 256) {
        int r = q >> 6;             // row in tile
        int f = q & 63;             // float4 index in stacked-K
        int row = blockRow + r;
        float4 v = make_float4(0.f, 0.f, 0.f, 0.f);
        if (row < M) {
            if (f < 32) {
                float dg = deg[row];
                float inv = 1.0f / fmaxf(dg, 1.0f);
                float4 a = ((const float4*)(agg + (long long)row * DD))[f];
                v = make_float4(a.x * inv, a.y * inv, a.z * inv, a.w * inv);
            } else {
                v = ((const float4*)(xin + (long long)row * DD))[f - 32];
            }
        }
        ((float4*)(Ash + r * 256))[f] = v;
    }
    __syncthreads();

    const int tx = tid & 31;
    const int ty = tid >> 5;
    float acc[8][4];
#pragma unroll
    for (int r = 0; r < 8; r++)
#pragma unroll
        for (int m = 0; m < 4; m++) acc[r][m] = 0.f;

    const float* Arow = Ash + (ty * 8) * 256;

#pragma unroll 2
    for (int k0 = 0; k0 < 256; k0 += 4) {
        float4 a[8];
#pragma unroll
        for (int r = 0; r < 8; r++)
            a[r] = *(const float4*)(Arow + r * 256 + k0);
        float w[4][4];
#pragma unroll
        for (int j = 0; j < 4; j++)
#pragma unroll
            for (int m = 0; m < 4; m++)
                w[j][m] = Wsh[(k0 + j) * WPAD + tx + m * 32];
#pragma unroll
        for (int r = 0; r < 8; r++)
#pragma unroll
            for (int m = 0; m < 4; m++) {
                acc[r][m] += a[r].x * w[0][m];
                acc[r][m] += a[r].y * w[1][m];
                acc[r][m] += a[r].z * w[2][m];
                acc[r][m] += a[r].w * w[3][m];
            }
    }

    // Epilogue
#pragma unroll
    for (int r = 0; r < 8; r++) {
        int row = blockRow + ty * 8 + r;
        if (row >= M) continue;
#pragma unroll
        for (int m = 0; m < 4; m++) {
            int c = tx + m * 32;
            float v = acc[r][m] + __ldg(bias + c);
            if (LAYER == 1) {
                v = fmaxf(v, 0.f);
                v = g_keep[(long long)row * DD + c] ? 2.f * v : 0.f;
            }
            out[(long long)row * DD + c] = v;
        }
    }
}

// ---------------- launch ----------------------------------------------------
extern "C" void kernel_launch(void* const* d_in, const int* in_sizes, int n_in,
                              void* d_out, int out_size) {
    // ---- identify inputs by SIZE RANKING (unit- and order-agnostic) ----
    // Descending by size: feat > t_adj > n_adj > {W1_l,W1_r,W2_l,W2_r} >
    // {b1,b2} > scalars. Among equal sizes keep encounter order (stable) —
    // dict order and alphabetical order agree on W and b sequences.
    int order[32];
    int m = n_in > 32 ? 32 : n_in;
    for (int k = 0; k < m; k++) order[k] = k;
    for (int a = 1; a < m; a++) {            // stable insertion sort, desc
        int key = order[a];
        int b = a - 1;
        while (b >= 0 && in_sizes[order[b]] < in_sizes[key]) {
            order[b + 1] = order[b];
            b--;
        }
        order[b + 1] = key;
    }

    const float* feat  = (const float*)d_in[order[0]];
    const void*  t_adj = d_in[order[1]];
    const void*  n_adj = d_in[order[2]];
    const float* W1l   = (const float*)d_in[order[3]];
    const float* W1r   = (const float*)d_in[order[4]];
    const float* W2l   = (const float*)d_in[order[5]];
    const float* W2r   = (const float*)d_in[order[6]];
    const float* b1    = (const float*)d_in[order[7]];
    const float* b2    = (const float*)d_in[order[8]];
    float* out = (float*)d_out;

    size_t smem = (size_t)(256 * WPAD + BM * 256) * sizeof(float);
    cudaFuncSetAttribute(gemm_kernel<1>, cudaFuncAttributeMaxDynamicSharedMemorySize, (int)smem);
    cudaFuncSetAttribute(gemm_kernel<2>, cudaFuncAttributeMaxDynamicSharedMemorySize, (int)smem);

    detect_kernel<<<1, 256>>>((const unsigned int*)t_adj, 4096);
    zero_kernel<<<592, 256>>>();
    mask_kernel<<<(MASK_CNT + 255) / 256, 256>>>();

    // Layer 1
    scatter_kernel<1><<<(E1_CNT * 32 + 255) / 256, 256>>>(feat, t_adj, E1_CNT);
    gemm_kernel<1><<<(JDIM + BM - 1) / BM, 256, smem>>>(feat, W1l, W1r, b1, nullptr);

    // Layer 2
    scatter_kernel<2><<<(E2_CNT * 32 + 255) / 256, 256>>>(nullptr, n_adj, E2_CNT);
    gemm_kernel<2><<<(IDIM + BM - 1) / BM, 256, smem>>>(nullptr, W2l, W2r, b2, out);
}

// round 10
// speedup vs baseline: 1.0369x; 1.0369x over previous
#include <cuda_runtime.h>
#include <cstdint>

// Problem-instance constants (fixed by setup_inputs)
#define NMAX 50000
#define JDIM 25000
#define IDIM 12500
#define DD   128
#define E1_CNT 600000
#define E2_CNT 300000
#define MASK_CNT (JDIM * DD)       // 3,200,000 dropout mask elements

// ---------------- scratch (device globals; no allocation allowed) ----------
__device__ __align__(16) float g_agg1[JDIM * DD];
__device__ __align__(16) float g_x1[JDIM * DD];
__device__ __align__(16) float g_agg2[IDIM * DD];
__device__ __align__(16) unsigned char g_keep[JDIM * DD];
__device__ int g_mode;   // 0 = int64, 1 = int32, 2 = float32

// CSR scratch
__device__ int g_cnt1[JDIM];
__device__ int g_off1[JDIM];
__device__ int g_pos1[JDIM];
__device__ int g_elist1[E1_CNT];
__device__ int g_cnt2[IDIM];
__device__ int g_off2[IDIM];
__device__ int g_pos2[IDIM];
__device__ int g_elist2[E2_CNT];

// ---------------- index-dtype detection ------------------------------------
__global__ void detect_kernel(const unsigned int* __restrict__ a, int nwords) {
    __shared__ int any_large, any_odd_nz;
    if (threadIdx.x == 0) { any_large = 0; any_odd_nz = 0; }
    __syncthreads();
    int limit = nwords < 4096 ? nwords : 4096;
    for (int t = threadIdx.x; t < limit; t += blockDim.x) {
        unsigned int w = a[t];
        if (w >= 0x40000000u) any_large = 1;
        if ((t & 1) && w != 0u) any_odd_nz = 1;
    }
    __syncthreads();
    if (threadIdx.x == 0)
        g_mode = any_large ? 2 : (any_odd_nz ? 1 : 0);
}

// ---------------- zero counters --------------------------------------------
__global__ void zero_kernel() {
    int i = blockIdx.x * blockDim.x + threadIdx.x;
    int stride = gridDim.x * blockDim.x;
    for (int t = i; t < JDIM; t += stride) g_cnt1[t] = 0;
    for (int t = i; t < IDIM; t += stride) g_cnt2[t] = 0;
}

// ---------------- threefry2x32 dropout mask (partitionable) ----------------
__global__ void mask_kernel() {
    int i = blockIdx.x * blockDim.x + threadIdx.x;
    if (i >= MASK_CNT) return;
    uint32_t x0 = 0u;               // hi 32 bits of counter
    uint32_t x1 = (uint32_t)i;      // lo 32 bits of counter
    const uint32_t ks0 = 0u, ks1 = 1u, ks2 = 0x1BD11BDBu;

#define TF_ROUND(r) { x0 += x1; x1 = __funnelshift_l(x1, x1, (r)); x1 ^= x0; }
#define TF_G0 TF_ROUND(13) TF_ROUND(15) TF_ROUND(26) TF_ROUND(6)
#define TF_G1 TF_ROUND(17) TF_ROUND(29) TF_ROUND(16) TF_ROUND(24)

    x0 += ks0; x1 += ks1;
    TF_G0
    x0 += ks1; x1 += ks2 + 1u;
    TF_G1
    x0 += ks2; x1 += ks0 + 2u;
    TF_G0
    x0 += ks0; x1 += ks1 + 3u;
    TF_G1
    x0 += ks1; x1 += ks2 + 4u;
    TF_G0
    x0 += ks2; x1 += ks0 + 5u;

    uint32_t bits = x0 ^ x1;        // partitionable 32-bit XOR-fold
    g_keep[i] = (unsigned char)(1u ^ (bits >> 31));
#undef TF_G1
#undef TF_G0
#undef TF_ROUND
}

// ---------------- edge decode helper ---------------------------------------
__device__ __forceinline__ void decode_edge(const void* ei_raw, int E, int w,
                                            long long& src, long long& dst) {
    int mode = g_mode;
    if (mode == 0) {
        const long long* ei = (const long long*)ei_raw;
        src = ei[w]; dst = ei[(long long)E + w];
    } else if (mode == 1) {
        const int* ei = (const int*)ei_raw;
        src = ei[w]; dst = ei[E + w];
    } else {
        const float* ei = (const float*)ei_raw;
        src = (long long)ei[w]; dst = (long long)ei[E + w];
    }
}

// ---------------- CSR build: count -----------------------------------------
template <int LAYER>
__global__ void count_kernel(const void* __restrict__ ei_raw, int E) {
    int w = blockIdx.x * blockDim.x + threadIdx.x;
    if (w >= E) return;
    long long src, dst;
    decode_edge(ei_raw, E, w, src, dst);
    const int dlim = (LAYER == 1) ? JDIM : IDIM;
    const int slim = (LAYER == 1) ? NMAX : JDIM;
    if ((unsigned long long)dst >= (unsigned long long)dlim) return;
    if ((unsigned long long)src >= (unsigned long long)slim) return;
    int* cnt = (LAYER == 1) ? g_cnt1 : g_cnt2;
    atomicAdd(cnt + (int)dst, 1);
}

// ---------------- CSR build: single-block scan ------------------------------
template <int LAYER>
__global__ void scan_kernel() {
    const int n = (LAYER == 1) ? JDIM : IDIM;
    const int* cnt = (LAYER == 1) ? g_cnt1 : g_cnt2;
    int* off = (LAYER == 1) ? g_off1 : g_off2;
    int* pos = (LAYER == 1) ? g_pos1 : g_pos2;

    __shared__ int s[1024];
    __shared__ int carry_sh;
    int tid = threadIdx.x;
    if (tid == 0) carry_sh = 0;
    __syncthreads();

    for (int base = 0; base < n; base += 1024) {
        int v = (base + tid < n) ? cnt[base + tid] : 0;
        s[tid] = v;
        __syncthreads();
        // Hillis-Steele inclusive scan
        for (int d = 1; d < 1024; d <<= 1) {
            int t = (tid >= d) ? s[tid - d] : 0;
            __syncthreads();
            s[tid] += t;
            __syncthreads();
        }
        int excl = s[tid] - v;
        int carry = carry_sh;
        if (base + tid < n) {
            off[base + tid] = carry + excl;
            pos[base + tid] = carry + excl;
        }
        __syncthreads();
        if (tid == 1023) carry_sh = carry + s[1023];
        __syncthreads();
    }
}

// ---------------- CSR build: fill -------------------------------------------
template <int LAYER>
__global__ void fill_kernel(const void* __restrict__ ei_raw, int E) {
    int w = blockIdx.x * blockDim.x + threadIdx.x;
    if (w >= E) return;
    long long src, dst;
    decode_edge(ei_raw, E, w, src, dst);
    const int dlim = (LAYER == 1) ? JDIM : IDIM;
    const int slim = (LAYER == 1) ? NMAX : JDIM;
    if ((unsigned long long)dst >= (unsigned long long)dlim) return;
    if ((unsigned long long)src >= (unsigned long long)slim) return;
    int* pos = (LAYER == 1) ? g_pos1 : g_pos2;
    int* elist = (LAYER == 1) ? g_elist1 : g_elist2;
    int slot = atomicAdd(pos + (int)dst, 1);
    elist[slot] = (int)src;
}

// ---------------- gather-mean: one warp per dst row -------------------------
template <int LAYER>
__global__ void gather_kernel(const float* __restrict__ xext) {
    const int M = (LAYER == 1) ? JDIM : IDIM;
    int row = (int)((blockIdx.x * (unsigned)blockDim.x + threadIdx.x) >> 5);
    if (row >= M) return;
    const int* off = (LAYER == 1) ? g_off1 : g_off2;
    const int* cnt = (LAYER == 1) ? g_cnt1 : g_cnt2;
    const int* elist = (LAYER == 1) ? g_elist1 : g_elist2;
    const float* x = (LAYER == 1) ? xext : g_x1;
    float* agg = (LAYER == 1) ? g_agg1 : g_agg2;

    int lane = threadIdx.x & 31;
    int start = off[row];
    int deg = cnt[row];

    float4 acc = make_float4(0.f, 0.f, 0.f, 0.f);
    int e = 0;
    // unrolled by 4 for MLP
    for (; e + 4 <= deg; e += 4) {
        int s0 = elist[start + e + 0];
        int s1 = elist[start + e + 1];
        int s2 = elist[start + e + 2];
        int s3 = elist[start + e + 3];
        float4 v0 = ((const float4*)(x + (long long)s0 * DD))[lane];
        float4 v1 = ((const float4*)(x + (long long)s1 * DD))[lane];
        float4 v2 = ((const float4*)(x + (long long)s2 * DD))[lane];
        float4 v3 = ((const float4*)(x + (long long)s3 * DD))[lane];
        acc.x += v0.x + v1.x + v2.x + v3.x;
        acc.y += v0.y + v1.y + v2.y + v3.y;
        acc.z += v0.z + v1.z + v2.z + v3.z;
        acc.w += v0.w + v1.w + v2.w + v3.w;
    }
    for (; e < deg; e++) {
        int s0 = elist[start + e];
        float4 v0 = ((const float4*)(x + (long long)s0 * DD))[lane];
        acc.x += v0.x; acc.y += v0.y; acc.z += v0.z; acc.w += v0.w;
    }
    float inv = 1.0f / fmaxf((float)deg, 1.0f);
    acc.x *= inv; acc.y *= inv; acc.z *= inv; acc.w *= inv;
    ((float4*)(agg + (long long)row * DD))[lane] = acc;
}

// ---------------- fused stacked GEMM ---------------------------------------
// out[r,c] = sum_k aggm[r,k]*Wl[c,k] + sum_k x[r,k]*Wr[c,k] + b[c]
#define WPAD 129    // padded row stride for Wsh (conflict-free)
#define BM   64     // rows per block

template <int LAYER>
__global__ __launch_bounds__(256, 1)
void gemm_kernel(const float* __restrict__ xext,
                 const float* __restrict__ Wl, const float* __restrict__ Wr,
                 const float* __restrict__ bias, float* __restrict__ outext) {
    extern __shared__ float sm[];
    float* Wsh = sm;                    // [256][WPAD]
    float* Ash = sm + 256 * WPAD;       // [BM][256]

    const int M = (LAYER == 1) ? JDIM : IDIM;
    const float* agg = (LAYER == 1) ? g_agg1 : g_agg2;
    const float* xin = (LAYER == 1) ? xext : g_x1;
    float* out = (LAYER == 1) ? g_x1 : outext;

    const int tid = threadIdx.x;
    const int blockRow = blockIdx.x * BM;

    // Load W stacked+transposed into Wsh[k][c], coalesced float4 along k.
    for (int q = tid; q < 8192; q += 256) {
        int m  = q >> 12;           // 0 = Wl, 1 = Wr
        int qq = q & 4095;
        int c  = qq >> 5;           // 0..127
        int kq = qq & 31;           // float4 index along k
        const float* src = (m ? Wr : Wl) + c * DD;
        float4 v = ((const float4*)src)[kq];
        int k0 = m * 128 + kq * 4;
        Wsh[(k0 + 0) * WPAD + c] = v.x;
        Wsh[(k0 + 1) * WPAD + c] = v.y;
        Wsh[(k0 + 2) * WPAD + c] = v.z;
        Wsh[(k0 + 3) * WPAD + c] = v.w;
    }

    // Load A tile [BM][256]: k<128 = agg (mean already applied), k>=128 = x.
    for (int q = tid; q < BM * 64; q += 256) {
        int r = q >> 6;             // row in tile
        int f = q & 63;             // float4 index in stacked-K
        int row = blockRow + r;
        float4 v = make_float4(0.f, 0.f, 0.f, 0.f);
        if (row < M) {
            if (f < 32) {
                v = ((const float4*)(agg + (long long)row * DD))[f];
            } else {
                v = ((const float4*)(xin + (long long)row * DD))[f - 32];
            }
        }
        ((float4*)(Ash + r * 256))[f] = v;
    }
    __syncthreads();

    const int tx = tid & 31;
    const int ty = tid >> 5;
    float acc[8][4];
#pragma unroll
    for (int r = 0; r < 8; r++)
#pragma unroll
        for (int m = 0; m < 4; m++) acc[r][m] = 0.f;

    const float* Arow = Ash + (ty * 8) * 256;

#pragma unroll 2
    for (int k0 = 0; k0 < 256; k0 += 4) {
        float4 a[8];
#pragma unroll
        for (int r = 0; r < 8; r++)
            a[r] = *(const float4*)(Arow + r * 256 + k0);
        float w[4][4];
#pragma unroll
        for (int j = 0; j < 4; j++)
#pragma unroll
            for (int m = 0; m < 4; m++)
                w[j][m] = Wsh[(k0 + j) * WPAD + tx + m * 32];
#pragma unroll
        for (int r = 0; r < 8; r++)
#pragma unroll
            for (int m = 0; m < 4; m++) {
                acc[r][m] += a[r].x * w[0][m];
                acc[r][m] += a[r].y * w[1][m];
                acc[r][m] += a[r].z * w[2][m];
                acc[r][m] += a[r].w * w[3][m];
            }
    }

    // Epilogue
#pragma unroll
    for (int r = 0; r < 8; r++) {
        int row = blockRow + ty * 8 + r;
        if (row >= M) continue;
#pragma unroll
        for (int m = 0; m < 4; m++) {
            int c = tx + m * 32;
            float v = acc[r][m] + __ldg(bias + c);
            if (LAYER == 1) {
                v = fmaxf(v, 0.f);
                v = g_keep[(long long)row * DD + c] ? 2.f * v : 0.f;
            }
            out[(long long)row * DD + c] = v;
        }
    }
}

// ---------------- launch ----------------------------------------------------
extern "C" void kernel_launch(void* const* d_in, const int* in_sizes, int n_in,
                              void* d_out, int out_size) {
    // ---- identify inputs by SIZE RANKING (unit- and order-agnostic) ----
    int order[32];
    int m = n_in > 32 ? 32 : n_in;
    for (int k = 0; k < m; k++) order[k] = k;
    for (int a = 1; a < m; a++) {            // stable insertion sort, desc
        int key = order[a];
        int b = a - 1;
        while (b >= 0 && in_sizes[order[b]] < in_sizes[key]) {
            order[b + 1] = order[b];
            b--;
        }
        order[b + 1] = key;
    }

    const float* feat  = (const float*)d_in[order[0]];
    const void*  t_adj = d_in[order[1]];
    const void*  n_adj = d_in[order[2]];
    const float* W1l   = (const float*)d_in[order[3]];
    const float* W1r   = (const float*)d_in[order[4]];
    const float* W2l   = (const float*)d_in[order[5]];
    const float* W2r   = (const float*)d_in[order[6]];
    const float* b1    = (const float*)d_in[order[7]];
    const float* b2    = (const float*)d_in[order[8]];
    float* out = (float*)d_out;

    size_t smem = (size_t)(256 * WPAD + BM * 256) * sizeof(float);
    cudaFuncSetAttribute(gemm_kernel<1>, cudaFuncAttributeMaxDynamicSharedMemorySize, (int)smem);
    cudaFuncSetAttribute(gemm_kernel<2>, cudaFuncAttributeMaxDynamicSharedMemorySize, (int)smem);

    detect_kernel<<<1, 256>>>((const unsigned int*)t_adj, 4096);
    zero_kernel<<<64, 256>>>();
    mask_kernel<<<(MASK_CNT + 255) / 256, 256>>>();

    // CSR build (both layers; independent of GEMMs)
    count_kernel<1><<<(E1_CNT + 255) / 256, 256>>>(t_adj, E1_CNT);
    count_kernel<2><<<(E2_CNT + 255) / 256, 256>>>(n_adj, E2_CNT);
    scan_kernel<1><<<1, 1024>>>();
    scan_kernel<2><<<1, 1024>>>();
    fill_kernel<1><<<(E1_CNT + 255) / 256, 256>>>(t_adj, E1_CNT);
    fill_kernel<2><<<(E2_CNT + 255) / 256, 256>>>(n_adj, E2_CNT);

    // Layer 1
    gather_kernel<1><<<(JDIM * 32 + 255) / 256, 256>>>(feat);
    gemm_kernel<1><<<(JDIM + BM - 1) / BM, 256, smem>>>(feat, W1l, W1r, b1, nullptr);

    // Layer 2
    gather_kernel<2><<<(IDIM * 32 + 255) / 256, 256>>>(nullptr);
    gemm_kernel<2><<<(IDIM + BM - 1) / BM, 256, smem>>>(nullptr, W2l, W2r, b2, out);
}

// round 12
// speedup vs baseline: 1.2562x; 1.2115x over previous
#include <cuda_runtime.h>
#include <cstdint>

#define NMAX 50000
#define JDIM 25000
#define IDIM 12500
#define DD   128
#define E1_CNT 600000
#define E2_CNT 300000
#define MASK_CNT (JDIM * DD)

#define MASK_BLK ((MASK_CNT + 255) / 256)   // 12500
#define C1_BLK   ((E1_CNT + 255) / 256)     // 2344
#define C2_BLK   ((E2_CNT + 255) / 256)     // 1172

// ---------------- scratch (device globals) ----------------------------------
__device__ __align__(16) float g_agg1[JDIM * DD];
__device__ __align__(16) float g_x1[JDIM * DD];
__device__ __align__(16) float g_agg2[IDIM * DD];
__device__ __align__(16) unsigned char g_keep[JDIM * DD];
__device__ int g_mode;

// CSR scratch
__device__ int g_cnt1[JDIM];
__device__ int g_off1[JDIM];
__device__ int g_pos1[JDIM];
__device__ int g_elist1[E1_CNT];
__device__ int g_cnt2[IDIM];
__device__ int g_off2[IDIM];
__device__ int g_pos2[IDIM];
__device__ int g_elist2[E2_CNT];

// ---------------- prep: zero counters + detect index dtype ------------------
__global__ void prep_kernel(const unsigned int* __restrict__ a) {
    int i = blockIdx.x * blockDim.x + threadIdx.x;
    int stride = gridDim.x * blockDim.x;
    for (int t = i; t < JDIM; t += stride) g_cnt1[t] = 0;
    for (int t = i; t < IDIM; t += stride) g_cnt2[t] = 0;

    if (blockIdx.x == 0) {
        __shared__ int any_large, any_odd_nz;
        if (threadIdx.x == 0) { any_large = 0; any_odd_nz = 0; }
        __syncthreads();
        for (int t = threadIdx.x; t < 4096; t += blockDim.x) {
            unsigned int w = a[t];
            if (w >= 0x40000000u) any_large = 1;
            if ((t & 1) && w != 0u) any_odd_nz = 1;
        }
        __syncthreads();
        if (threadIdx.x == 0)
            g_mode = any_large ? 2 : (any_odd_nz ? 1 : 0);
    }
}

// ---------------- edge decode ------------------------------------------------
__device__ __forceinline__ void decode_edge(const void* ei_raw, int E, int w,
                                            long long& src, long long& dst) {
    int mode = g_mode;
    if (mode == 0) {
        const long long* ei = (const long long*)ei_raw;
        src = ei[w]; dst = ei[(long long)E + w];
    } else if (mode == 1) {
        const int* ei = (const int*)ei_raw;
        src = ei[w]; dst = ei[E + w];
    } else {
        const float* ei = (const float*)ei_raw;
        src = (long long)ei[w]; dst = (long long)ei[E + w];
    }
}

__device__ __forceinline__ void count_edge(const void* ei_raw, int E, int w,
                                           int dlim, int slim, int* cnt) {
    if (w >= E) return;
    long long src, dst;
    decode_edge(ei_raw, E, w, src, dst);
    if ((unsigned long long)dst >= (unsigned long long)dlim) return;
    if ((unsigned long long)src >= (unsigned long long)slim) return;
    atomicAdd(cnt + (int)dst, 1);
}

// ---------------- fused mask + count1 + count2 -------------------------------
__global__ void maskcount_kernel(const void* __restrict__ t_adj,
                                 const void* __restrict__ n_adj) {
    int bid = blockIdx.x;
    if (bid < MASK_BLK) {
        int i = bid * 256 + threadIdx.x;
        if (i >= MASK_CNT) return;
        uint32_t x0 = 0u;
        uint32_t x1 = (uint32_t)i;
        const uint32_t ks0 = 0u, ks1 = 1u, ks2 = 0x1BD11BDBu;

#define TF_ROUND(r) { x0 += x1; x1 = __funnelshift_l(x1, x1, (r)); x1 ^= x0; }
#define TF_G0 TF_ROUND(13) TF_ROUND(15) TF_ROUND(26) TF_ROUND(6)
#define TF_G1 TF_ROUND(17) TF_ROUND(29) TF_ROUND(16) TF_ROUND(24)

        x0 += ks0; x1 += ks1;
        TF_G0
        x0 += ks1; x1 += ks2 + 1u;
        TF_G1
        x0 += ks2; x1 += ks0 + 2u;
        TF_G0
        x0 += ks0; x1 += ks1 + 3u;
        TF_G1
        x0 += ks1; x1 += ks2 + 4u;
        TF_G0
        x0 += ks2; x1 += ks0 + 5u;

        uint32_t bits = x0 ^ x1;
        g_keep[i] = (unsigned char)(1u ^ (bits >> 31));
#undef TF_G1
#undef TF_G0
#undef TF_ROUND
    } else if (bid < MASK_BLK + C1_BLK) {
        int w = (bid - MASK_BLK) * 256 + threadIdx.x;
        count_edge(t_adj, E1_CNT, w, JDIM, NMAX, g_cnt1);
    } else {
        int w = (bid - MASK_BLK - C1_BLK) * 256 + threadIdx.x;
        count_edge(n_adj, E2_CNT, w, IDIM, JDIM, g_cnt2);
    }
}

// ---------------- fused scan (block 0 = layer1, block 1 = layer2) -----------
__global__ void scan_kernel() {
    const int layer = blockIdx.x;
    const int n = (layer == 0) ? JDIM : IDIM;
    const int* cnt = (layer == 0) ? g_cnt1 : g_cnt2;
    int* off = (layer == 0) ? g_off1 : g_off2;
    int* pos = (layer == 0) ? g_pos1 : g_pos2;

    __shared__ int warp_sums[32];
    __shared__ int carry_sh;
    int tid = threadIdx.x;
    int lane = tid & 31;
    int wid = tid >> 5;
    if (tid == 0) carry_sh = 0;
    __syncthreads();

    for (int base = 0; base < n; base += 1024) {
        int v = (base + tid < n) ? cnt[base + tid] : 0;
        int x = v;
#pragma unroll
        for (int d = 1; d < 32; d <<= 1) {
            int t = __shfl_up_sync(0xFFFFFFFFu, x, d);
            if (lane >= d) x += t;
        }
        if (lane == 31) warp_sums[wid] = x;
        __syncthreads();
        if (wid == 0) {
            int s = warp_sums[lane];
#pragma unroll
            for (int d = 1; d < 32; d <<= 1) {
                int t = __shfl_up_sync(0xFFFFFFFFu, s, d);
                if (lane >= d) s += t;
            }
            warp_sums[lane] = s;
        }
        __syncthreads();
        int warp_excl = (wid == 0) ? 0 : warp_sums[wid - 1];
        int incl = x + warp_excl;
        int excl = incl - v;
        int c = carry_sh;
        if (base + tid < n) {
            off[base + tid] = c + excl;
            pos[base + tid] = c + excl;
        }
        __syncthreads();
        if (tid == 1023) carry_sh = c + incl;
        __syncthreads();
    }
}

// ---------------- fused fill1 + fill2 ---------------------------------------
__device__ __forceinline__ void fill_edge(const void* ei_raw, int E, int w,
                                          int dlim, int slim, int* pos, int* elist) {
    if (w >= E) return;
    long long src, dst;
    decode_edge(ei_raw, E, w, src, dst);
    if ((unsigned long long)dst >= (unsigned long long)dlim) return;
    if ((unsigned long long)src >= (unsigned long long)slim) return;
    int slot = atomicAdd(pos + (int)dst, 1);
    elist[slot] = (int)src;
}

__global__ void fill_kernel(const void* __restrict__ t_adj,
                            const void* __restrict__ n_adj) {
    int bid = blockIdx.x;
    if (bid < C1_BLK) {
        int w = bid * 256 + threadIdx.x;
        fill_edge(t_adj, E1_CNT, w, JDIM, NMAX, g_pos1, g_elist1);
    } else {
        int w = (bid - C1_BLK) * 256 + threadIdx.x;
        fill_edge(n_adj, E2_CNT, w, IDIM, JDIM, g_pos2, g_elist2);
    }
}

// ---------------- gather-mean: one warp per dst row --------------------------
template <int LAYER>
__global__ void gather_kernel(const float* __restrict__ xext) {
    const int M = (LAYER == 1) ? JDIM : IDIM;
    int row = (int)((blockIdx.x * (unsigned)blockDim.x + threadIdx.x) >> 5);
    if (row >= M) return;
    const int* off = (LAYER == 1) ? g_off1 : g_off2;
    const int* cnt = (LAYER == 1) ? g_cnt1 : g_cnt2;
    const int* elist = (LAYER == 1) ? g_elist1 : g_elist2;
    const float* x = (LAYER == 1) ? xext : g_x1;
    float* agg = (LAYER == 1) ? g_agg1 : g_agg2;

    int lane = threadIdx.x & 31;
    int start = off[row];
    int deg = cnt[row];

    float4 acc = make_float4(0.f, 0.f, 0.f, 0.f);
    int e = 0;
    for (; e + 4 <= deg; e += 4) {
        int s0 = elist[start + e + 0];
        int s1 = elist[start + e + 1];
        int s2 = elist[start + e + 2];
        int s3 = elist[start + e + 3];
        float4 v0 = ((const float4*)(x + (long long)s0 * DD))[lane];
        float4 v1 = ((const float4*)(x + (long long)s1 * DD))[lane];
        float4 v2 = ((const float4*)(x + (long long)s2 * DD))[lane];
        float4 v3 = ((const float4*)(x + (long long)s3 * DD))[lane];
        acc.x += v0.x + v1.x + v2.x + v3.x;
        acc.y += v0.y + v1.y + v2.y + v3.y;
        acc.z += v0.z + v1.z + v2.z + v3.z;
        acc.w += v0.w + v1.w + v2.w + v3.w;
    }
    for (; e < deg; e++) {
        int s0 = elist[start + e];
        float4 v0 = ((const float4*)(x + (long long)s0 * DD))[lane];
        acc.x += v0.x; acc.y += v0.y; acc.z += v0.z; acc.w += v0.w;
    }
    float inv = 1.0f / fmaxf((float)deg, 1.0f);
    acc.x *= inv; acc.y *= inv; acc.z *= inv; acc.w *= inv;
    ((float4*)(agg + (long long)row * DD))[lane] = acc;
}

// ---------------- fused stacked GEMM (K=256) --------------------------------
// out[r,c] = sum_k aggm[r,k]*Wl[c,k] + sum_k x[r,k]*Wr[c,k] + b[c]
#define WPAD 129
#define BM   64

template <int LAYER>
__global__ __launch_bounds__(256, 1)
void gemm_kernel(const float* __restrict__ xext,
                 const float* __restrict__ Wl, const float* __restrict__ Wr,
                 const float* __restrict__ bias, float* __restrict__ outext) {
    extern __shared__ float sm[];
    float* Wsh = sm;                    // [256][WPAD]
    float* Ash = sm + 256 * WPAD;       // [BM][256]

    const int M = (LAYER == 1) ? JDIM : IDIM;
    const float* agg = (LAYER == 1) ? g_agg1 : g_agg2;
    const float* xin = (LAYER == 1) ? xext : g_x1;
    float* out = (LAYER == 1) ? g_x1 : outext;

    const int tid = threadIdx.x;
    const int blockRow = blockIdx.x * BM;

    for (int q = tid; q < 8192; q += 256) {
        int m  = q >> 12;
        int qq = q & 4095;
        int c  = qq >> 5;
        int kq = qq & 31;
        const float* src = (m ? Wr : Wl) + c * DD;
        float4 v = ((const float4*)src)[kq];
        int k0 = m * 128 + kq * 4;
        Wsh[(k0 + 0) * WPAD + c] = v.x;
        Wsh[(k0 + 1) * WPAD + c] = v.y;
        Wsh[(k0 + 2) * WPAD + c] = v.z;
        Wsh[(k0 + 3) * WPAD + c] = v.w;
    }

    for (int q = tid; q < BM * 64; q += 256) {
        int r = q >> 6;
        int f = q & 63;
        int row = blockRow + r;
        float4 v = make_float4(0.f, 0.f, 0.f, 0.f);
        if (row < M) {
            if (f < 32) {
                v = ((const float4*)(agg + (long long)row * DD))[f];
            } else {
                v = ((const float4*)(xin + (long long)row * DD))[f - 32];
            }
        }
        ((float4*)(Ash + r * 256))[f] = v;
    }
    __syncthreads();

    const int tx = tid & 31;
    const int ty = tid >> 5;
    float acc[8][4];
#pragma unroll
    for (int r = 0; r < 8; r++)
#pragma unroll
        for (int m = 0; m < 4; m++) acc[r][m] = 0.f;

    const float* Arow = Ash + (ty * 8) * 256;

#pragma unroll 2
    for (int k0 = 0; k0 < 256; k0 += 4) {
        float4 a[8];
#pragma unroll
        for (int r = 0; r < 8; r++)
            a[r] = *(const float4*)(Arow + r * 256 + k0);
        float w[4][4];
#pragma unroll
        for (int j = 0; j < 4; j++)
#pragma unroll
            for (int m = 0; m < 4; m++)
                w[j][m] = Wsh[(k0 + j) * WPAD + tx + m * 32];
#pragma unroll
        for (int r = 0; r < 8; r++)
#pragma unroll
            for (int m = 0; m < 4; m++) {
                acc[r][m] += a[r].x * w[0][m];
                acc[r][m] += a[r].y * w[1][m];
                acc[r][m] += a[r].z * w[2][m];
                acc[r][m] += a[r].w * w[3][m];
            }
    }

#pragma unroll
    for (int r = 0; r < 8; r++) {
        int row = blockRow + ty * 8 + r;
        if (row >= M) continue;
#pragma unroll
        for (int m = 0; m < 4; m++) {
            int c = tx + m * 32;
            float v = acc[r][m] + __ldg(bias + c);
            if (LAYER == 1) {
                v = fmaxf(v, 0.f);
                v = g_keep[(long long)row * DD + c] ? 2.f * v : 0.f;
            }
            out[(long long)row * DD + c] = v;
        }
    }
}

// ---------------- launch -----------------------------------------------------
extern "C" void kernel_launch(void* const* d_in, const int* in_sizes, int n_in,
                              void* d_out, int out_size) {
    // identify inputs by size ranking (stable, unit-agnostic)
    int order[32];
    int m = n_in > 32 ? 32 : n_in;
    for (int k = 0; k < m; k++) order[k] = k;
    for (int a = 1; a < m; a++) {
        int key = order[a];
        int b = a - 1;
        while (b >= 0 && in_sizes[order[b]] < in_sizes[key]) {
            order[b + 1] = order[b];
            b--;
        }
        order[b + 1] = key;
    }
    const float* feat  = (const float*)d_in[order[0]];
    const void*  t_adj = d_in[order[1]];
    const void*  n_adj = d_in[order[2]];
    const float* W1l   = (const float*)d_in[order[3]];
    const float* W1r   = (const float*)d_in[order[4]];
    const float* W2l   = (const float*)d_in[order[5]];
    const float* W2r   = (const float*)d_in[order[6]];
    const float* b1    = (const float*)d_in[order[7]];
    const float* b2    = (const float*)d_in[order[8]];
    float* out = (float*)d_out;

    size_t smem = (size_t)(256 * WPAD + BM * 256) * sizeof(float);
    cudaFuncSetAttribute(gemm_kernel<1>, cudaFuncAttributeMaxDynamicSharedMemorySize, (int)smem);
    cudaFuncSetAttribute(gemm_kernel<2>, cudaFuncAttributeMaxDynamicSharedMemorySize, (int)smem);

    prep_kernel<<<64, 256>>>((const unsigned int*)t_adj);
    maskcount_kernel<<<MASK_BLK + C1_BLK + C2_BLK, 256>>>(t_adj, n_adj);
    scan_kernel<<<2, 1024>>>();
    fill_kernel<<<C1_BLK + C2_BLK, 256>>>(t_adj, n_adj);

    // Layer 1
    gather_kernel<1><<<(JDIM * 32 + 255) / 256, 256>>>(feat);
    gemm_kernel<1><<<(JDIM + BM - 1) / BM, 256, smem>>>(feat, W1l, W1r, b1, nullptr);

    // Layer 2
    gather_kernel<2><<<(IDIM * 32 + 255) / 256, 256>>>(nullptr);
    gemm_kernel<2><<<(IDIM + BM - 1) / BM, 256, smem>>>(nullptr, W2l, W2r, b2, out);
}

// round 15
// speedup vs baseline: 1.4478x; 1.1525x over previous
#include <cuda_runtime.h>
#include <cstdint>

#define NMAX 50000
#define JDIM 25000
#define IDIM 12500
#define DD   128
#define E1_CNT 600000
#define E2_CNT 300000
#define MASK_CNT (JDIM * DD)

#define MASK_BLK ((MASK_CNT + 255) / 256)   // 12500
#define C1_BLK   ((E1_CNT + 255) / 256)     // 2344
#define C2_BLK   ((E2_CNT + 255) / 256)     // 1172

// ---------------- scratch (device globals; referenced ONLY in device code) --
__device__ __align__(16) float g_agg1[JDIM * DD];
__device__ __align__(16) float g_x1[JDIM * DD];
__device__ __align__(16) float g_agg2[IDIM * DD];
__device__ __align__(16) unsigned char g_keep[JDIM * DD];
__device__ int g_mode;

// CSR scratch
__device__ int g_cnt1[JDIM];
__device__ int g_off1[JDIM];
__device__ int g_pos1[JDIM];
__device__ int g_elist1[E1_CNT];
__device__ int g_cnt2[IDIM];
__device__ int g_off2[IDIM];
__device__ int g_pos2[IDIM];
__device__ int g_elist2[E2_CNT];

// ---------------- prep: zero counters + detect index dtype ------------------
__global__ void prep_kernel(const unsigned int* __restrict__ a) {
    int i = blockIdx.x * blockDim.x + threadIdx.x;
    int stride = gridDim.x * blockDim.x;
    for (int t = i; t < JDIM; t += stride) g_cnt1[t] = 0;
    for (int t = i; t < IDIM; t += stride) g_cnt2[t] = 0;

    if (blockIdx.x == 0) {
        __shared__ int any_large, any_odd_nz;
        if (threadIdx.x == 0) { any_large = 0; any_odd_nz = 0; }
        __syncthreads();
        for (int t = threadIdx.x; t < 4096; t += blockDim.x) {
            unsigned int w = a[t];
            if (w >= 0x40000000u) any_large = 1;
            if ((t & 1) && w != 0u) any_odd_nz = 1;
        }
        __syncthreads();
        if (threadIdx.x == 0)
            g_mode = any_large ? 2 : (any_odd_nz ? 1 : 0);
    }
}

// ---------------- edge decode ------------------------------------------------
__device__ __forceinline__ void decode_edge(const void* ei_raw, int E, int w,
                                            long long& src, long long& dst) {
    int mode = g_mode;
    if (mode == 0) {
        const long long* ei = (const long long*)ei_raw;
        src = ei[w]; dst = ei[(long long)E + w];
    } else if (mode == 1) {
        const int* ei = (const int*)ei_raw;
        src = ei[w]; dst = ei[E + w];
    } else {
        const float* ei = (const float*)ei_raw;
        src = (long long)ei[w]; dst = (long long)ei[E + w];
    }
}

__device__ __forceinline__ void count_edge(const void* ei_raw, int E, int w,
                                           int dlim, int slim, int* cnt) {
    if (w >= E) return;
    long long src, dst;
    decode_edge(ei_raw, E, w, src, dst);
    if ((unsigned long long)dst >= (unsigned long long)dlim) return;
    if ((unsigned long long)src >= (unsigned long long)slim) return;
    atomicAdd(cnt + (int)dst, 1);
}

// ---------------- fused mask + count1 + count2 -------------------------------
__global__ void maskcount_kernel(const void* __restrict__ t_adj,
                                 const void* __restrict__ n_adj) {
    int bid = blockIdx.x;
    if (bid < MASK_BLK) {
        int i = bid * 256 + threadIdx.x;
        if (i >= MASK_CNT) return;
        uint32_t x0 = 0u;
        uint32_t x1 = (uint32_t)i;
        const uint32_t ks0 = 0u, ks1 = 1u, ks2 = 0x1BD11BDBu;

#define TF_ROUND(r) { x0 += x1; x1 = __funnelshift_l(x1, x1, (r)); x1 ^= x0; }
#define TF_G0 TF_ROUND(13) TF_ROUND(15) TF_ROUND(26) TF_ROUND(6)
#define TF_G1 TF_ROUND(17) TF_ROUND(29) TF_ROUND(16) TF_ROUND(24)

        x0 += ks0; x1 += ks1;
        TF_G0
        x0 += ks1; x1 += ks2 + 1u;
        TF_G1
        x0 += ks2; x1 += ks0 + 2u;
        TF_G0
        x0 += ks0; x1 += ks1 + 3u;
        TF_G1
        x0 += ks1; x1 += ks2 + 4u;
        TF_G0
        x0 += ks2; x1 += ks0 + 5u;

        uint32_t bits = x0 ^ x1;
        g_keep[i] = (unsigned char)(1u ^ (bits >> 31));
#undef TF_G1
#undef TF_G0
#undef TF_ROUND
    } else if (bid < MASK_BLK + C1_BLK) {
        int w = (bid - MASK_BLK) * 256 + threadIdx.x;
        count_edge(t_adj, E1_CNT, w, JDIM, NMAX, g_cnt1);
    } else {
        int w = (bid - MASK_BLK - C1_BLK) * 256 + threadIdx.x;
        count_edge(n_adj, E2_CNT, w, IDIM, JDIM, g_cnt2);
    }
}

// ---------------- fused scan (block 0 = layer1, block 1 = layer2) -----------
__global__ void scan_kernel() {
    const int layer = blockIdx.x;
    const int n = (layer == 0) ? JDIM : IDIM;
    const int* cnt = (layer == 0) ? g_cnt1 : g_cnt2;
    int* off = (layer == 0) ? g_off1 : g_off2;
    int* pos = (layer == 0) ? g_pos1 : g_pos2;

    __shared__ int warp_sums[32];
    __shared__ int carry_sh;
    int tid = threadIdx.x;
    int lane = tid & 31;
    int wid = tid >> 5;
    if (tid == 0) carry_sh = 0;
    __syncthreads();

    for (int base = 0; base < n; base += 1024) {
        int v = (base + tid < n) ? cnt[base + tid] : 0;
        int x = v;
#pragma unroll
        for (int d = 1; d < 32; d <<= 1) {
            int t = __shfl_up_sync(0xFFFFFFFFu, x, d);
            if (lane >= d) x += t;
        }
        if (lane == 31) warp_sums[wid] = x;
        __syncthreads();
        if (wid == 0) {
            int s = warp_sums[lane];
#pragma unroll
            for (int d = 1; d < 32; d <<= 1) {
                int t = __shfl_up_sync(0xFFFFFFFFu, s, d);
                if (lane >= d) s += t;
            }
            warp_sums[lane] = s;
        }
        __syncthreads();
        int warp_excl = (wid == 0) ? 0 : warp_sums[wid - 1];
        int incl = x + warp_excl;
        int excl = incl - v;
        int c = carry_sh;
        if (base + tid < n) {
            off[base + tid] = c + excl;
            pos[base + tid] = c + excl;
        }
        __syncthreads();
        if (tid == 1023) carry_sh = c + incl;
        __syncthreads();
    }
}

// ---------------- fused fill1 + fill2 ---------------------------------------
__device__ __forceinline__ void fill_edge(const void* ei_raw, int E, int w,
                                          int dlim, int slim, int* pos, int* elist) {
    if (w >= E) return;
    long long src, dst;
    decode_edge(ei_raw, E, w, src, dst);
    if ((unsigned long long)dst >= (unsigned long long)dlim) return;
    if ((unsigned long long)src >= (unsigned long long)slim) return;
    int slot = atomicAdd(pos + (int)dst, 1);
    elist[slot] = (int)src;
}

__global__ void fill_kernel(const void* __restrict__ t_adj,
                            const void* __restrict__ n_adj) {
    int bid = blockIdx.x;
    if (bid < C1_BLK) {
        int w = bid * 256 + threadIdx.x;
        fill_edge(t_adj, E1_CNT, w, JDIM, NMAX, g_pos1, g_elist1);
    } else {
        int w = (bid - C1_BLK) * 256 + threadIdx.x;
        fill_edge(n_adj, E2_CNT, w, IDIM, JDIM, g_pos2, g_elist2);
    }
}

// ---------------- gather-mean: one warp per dst row --------------------------
template <int LAYER>
__global__ void gather_kernel(const float* __restrict__ xext) {
    const int M = (LAYER == 1) ? JDIM : IDIM;
    int row = (int)((blockIdx.x * (unsigned)blockDim.x + threadIdx.x) >> 5);
    if (row >= M) return;
    const int* off = (LAYER == 1) ? g_off1 : g_off2;
    const int* cnt = (LAYER == 1) ? g_cnt1 : g_cnt2;
    const int* elist = (LAYER == 1) ? g_elist1 : g_elist2;
    const float* x = (LAYER == 1) ? xext : g_x1;
    float* agg = (LAYER == 1) ? g_agg1 : g_agg2;

    int lane = threadIdx.x & 31;
    int start = off[row];
    int deg = cnt[row];

    float4 acc = make_float4(0.f, 0.f, 0.f, 0.f);
    int e = 0;
    for (; e + 4 <= deg; e += 4) {
        int s0 = elist[start + e + 0];
        int s1 = elist[start + e + 1];
        int s2 = elist[start + e + 2];
        int s3 = elist[start + e + 3];
        float4 v0 = ((const float4*)(x + (long long)s0 * DD))[lane];
        float4 v1 = ((const float4*)(x + (long long)s1 * DD))[lane];
        float4 v2 = ((const float4*)(x + (long long)s2 * DD))[lane];
        float4 v3 = ((const float4*)(x + (long long)s3 * DD))[lane];
        acc.x += v0.x + v1.x + v2.x + v3.x;
        acc.y += v0.y + v1.y + v2.y + v3.y;
        acc.z += v0.z + v1.z + v2.z + v3.z;
        acc.w += v0.w + v1.w + v2.w + v3.w;
    }
    for (; e < deg; e++) {
        int s0 = elist[start + e];
        float4 v0 = ((const float4*)(x + (long long)s0 * DD))[lane];
        acc.x += v0.x; acc.y += v0.y; acc.z += v0.z; acc.w += v0.w;
    }
    float inv = 1.0f / fmaxf((float)deg, 1.0f);
    acc.x *= inv; acc.y *= inv; acc.z *= inv; acc.w *= inv;
    ((float4*)(agg + (long long)row * DD))[lane] = acc;
}

// ---------------- f32x2 packed-FMA GEMM --------------------------------------
// MODE 1: g_x1 = dropout(relu(g_agg1@W1^T + xext@W2^T + bias))   (xext = feat)
// MODE 2: outext = g_agg2@W1^T + g_x1@W2^T + bias
// Block: 64 rows x 128 cols, 128 threads, thread tile 8r x 8c (4 f32x2 pairs).
#define WST 130                       // Wsh row stride (even -> b64-aligned)
#define GB_SMEM ((64 * 128 + 128 * WST) * 4)   // 99328 B

__device__ __forceinline__ void fma2(unsigned long long& d,
                                     unsigned long long a, unsigned long long b) {
    asm("fma.rn.f32x2 %0, %1, %2, %0;" : "+l"(d) : "l"(a), "l"(b));
}
__device__ __forceinline__ unsigned long long dup2(float f) {
    unsigned long long r;
    asm("mov.b64 %0, {%1, %1};" : "=l"(r) : "f"(f));
    return r;
}
__device__ __forceinline__ float2 unpack2(unsigned long long v) {
    float2 r;
    asm("mov.b64 {%0, %1}, %2;" : "=f"(r.x), "=f"(r.y) : "l"(v));
    return r;
}

template <int MODE>
__global__ __launch_bounds__(128, 2)
void gemm_kernel(const float* __restrict__ xext,
                 const float* __restrict__ W1, const float* __restrict__ W2,
                 const float* __restrict__ bias, float* __restrict__ outext, int M) {
    extern __shared__ float sm[];
    float* Ash = sm;                  // [64][128]
    float* Wsh = sm + 64 * 128;       // [128][WST]

    // scratch pointers resolved IN DEVICE CODE (host must never pass them)
    const float* A1 = (MODE == 1) ? g_agg1 : g_agg2;
    const float* A2 = (MODE == 1) ? xext   : g_x1;
    float* out      = (MODE == 1) ? g_x1   : outext;

    const int tid = threadIdx.x;
    const int tx = tid & 15;          // 16 x 8 cols = 128 cols
    const int ty = tid >> 4;          // 8  x 8 rows = 64 rows
    const int blockRow = blockIdx.x * 64;

    unsigned long long acc[8][4];
#pragma unroll
    for (int r = 0; r < 8; r++)
#pragma unroll
        for (int p = 0; p < 4; p++) acc[r][p] = 0ULL;

#pragma unroll
    for (int phase = 0; phase < 2; phase++) {
        const float* A = phase ? A2 : A1;
        const float* W = phase ? W2 : W1;
        if (phase) __syncthreads();   // all reads of previous tiles done

        // A tile: [64 rows][128 k], float4 along k (coalesced)
        for (int q = tid; q < 64 * 32; q += 128) {
            int r = q >> 5;
            int f = q & 31;
            int row = blockRow + r;
            float4 v = make_float4(0.f, 0.f, 0.f, 0.f);
            if (row < M) v = ((const float4*)(A + (long long)row * DD))[f];
            ((float4*)(Ash + r * 128))[f] = v;
        }
        // W[c][k] -> Wsh[k][c] (transposed)
        for (int q = tid; q < 128 * 32; q += 128) {
            int c  = q >> 5;
            int kq = q & 31;
            float4 v = ((const float4*)(W + c * DD))[kq];
            int k0 = kq * 4;
            Wsh[(k0 + 0) * WST + c] = v.x;
            Wsh[(k0 + 1) * WST + c] = v.y;
            Wsh[(k0 + 2) * WST + c] = v.z;
            Wsh[(k0 + 3) * WST + c] = v.w;
        }
        __syncthreads();

#pragma unroll 2
        for (int k0 = 0; k0 < 128; k0 += 4) {
            float4 a4[8];
#pragma unroll
            for (int r = 0; r < 8; r++)
                a4[r] = *(const float4*)(Ash + (ty * 8 + r) * 128 + k0);
#pragma unroll
            for (int kk = 0; kk < 4; kk++) {
                const unsigned long long* wrow =
                    (const unsigned long long*)(Wsh + (k0 + kk) * WST + tx * 8);
                unsigned long long w2[4];
#pragma unroll
                for (int p = 0; p < 4; p++) w2[p] = wrow[p];
#pragma unroll
                for (int r = 0; r < 8; r++) {
                    float av = (kk == 0) ? a4[r].x : (kk == 1) ? a4[r].y
                              : (kk == 2) ? a4[r].z : a4[r].w;
                    unsigned long long a2 = dup2(av);
#pragma unroll
                    for (int p = 0; p < 4; p++) fma2(acc[r][p], a2, w2[p]);
                }
            }
        }
    }

    // epilogue
#pragma unroll
    for (int r = 0; r < 8; r++) {
        int row = blockRow + ty * 8 + r;
        if (row >= M) continue;
        long long base = (long long)row * DD + tx * 8;
        float res[8];
#pragma unroll
        for (int p = 0; p < 4; p++) {
            float2 v = unpack2(acc[r][p]);
            int c = tx * 8 + p * 2;
            res[p * 2 + 0] = v.x + __ldg(bias + c + 0);
            res[p * 2 + 1] = v.y + __ldg(bias + c + 1);
        }
        if (MODE == 1) {
            uint32_t kp0 = *(const uint32_t*)(g_keep + base);
            uint32_t kp1 = *(const uint32_t*)(g_keep + base + 4);
#pragma unroll
            for (int j = 0; j < 4; j++) {
                res[j]     = ((kp0 >> (j * 8)) & 0xFFu) ? 2.f * fmaxf(res[j], 0.f)     : 0.f;
                res[j + 4] = ((kp1 >> (j * 8)) & 0xFFu) ? 2.f * fmaxf(res[j + 4], 0.f) : 0.f;
            }
        }
        *(float4*)(out + base)     = make_float4(res[0], res[1], res[2], res[3]);
        *(float4*)(out + base + 4) = make_float4(res[4], res[5], res[6], res[7]);
    }
}

// ---------------- launch -----------------------------------------------------
extern "C" void kernel_launch(void* const* d_in, const int* in_sizes, int n_in,
                              void* d_out, int out_size) {
    // identify inputs by size ranking (stable, unit-agnostic)
    int order[32];
    int m = n_in > 32 ? 32 : n_in;
    for (int k = 0; k < m; k++) order[k] = k;
    for (int a = 1; a < m; a++) {
        int key = order[a];
        int b = a - 1;
        while (b >= 0 && in_sizes[order[b]] < in_sizes[key]) {
            order[b + 1] = order[b];
            b--;
        }
        order[b + 1] = key;
    }
    const float* feat  = (const float*)d_in[order[0]];
    const void*  t_adj = d_in[order[1]];
    const void*  n_adj = d_in[order[2]];
    const float* W1l   = (const float*)d_in[order[3]];
    const float* W1r   = (const float*)d_in[order[4]];
    const float* W2l   = (const float*)d_in[order[5]];
    const float* W2r   = (const float*)d_in[order[6]];
    const float* b1    = (const float*)d_in[order[7]];
    const float* b2    = (const float*)d_in[order[8]];
    float* out = (float*)d_out;

    cudaFuncSetAttribute(gemm_kernel<1>, cudaFuncAttributeMaxDynamicSharedMemorySize, GB_SMEM);
    cudaFuncSetAttribute(gemm_kernel<2>, cudaFuncAttributeMaxDynamicSharedMemorySize, GB_SMEM);

    prep_kernel<<<64, 256>>>((const unsigned int*)t_adj);
    maskcount_kernel<<<MASK_BLK + C1_BLK + C2_BLK, 256>>>(t_adj, n_adj);
    scan_kernel<<<2, 1024>>>();
    fill_kernel<<<C1_BLK + C2_BLK, 256>>>(t_adj, n_adj);

    // Layer 1: x1 = dropout(relu(agg1@W1l^T + feat@W1r^T + b1))
    gather_kernel<1><<<(JDIM * 32 + 255) / 256, 256>>>(feat);
    gemm_kernel<1><<<(JDIM + 63) / 64, 128, GB_SMEM>>>(feat, W1l, W1r, b1, nullptr, JDIM);

    // Layer 2: out = agg2@W2l^T + x1@W2r^T + b2
    gather_kernel<2><<<(IDIM * 32 + 255) / 256, 256>>>(nullptr);
    gemm_kernel<2><<<(IDIM + 63) / 64, 128, GB_SMEM>>>(nullptr, W2l, W2r, b2, out, IDIM);
}